// round 1
// baseline (speedup 1.0000x reference)
#include <cuda_runtime.h>

#define BATCH   2048
#define IN_DIM  512
#define OUT_DIM 512
#define SDIM    8
#define KDIM    (SDIM * IN_DIM)   // 4096
#define ROWLEN  (IN_DIM + 1)      // 513

#define BM 128
#define BN 64
#define BK 16
#define TM 8
#define TN 4
#define NTHREADS 256
#define SA_STRIDE (BM + 4)        // pad to avoid STS bank conflicts, keeps 16B align
#define NTILES (KDIM / BK)        // 256

// ---------------------------------------------------------------------------
// Scratch: per-row truncated power basis (2048 x 8)
// ---------------------------------------------------------------------------
__device__ float g_basis[BATCH * SDIM];

__global__ void basis_kernel(const float* __restrict__ inputs) {
    int b = blockIdx.x * blockDim.x + threadIdx.x;
    if (b >= BATCH) return;
    float t  = inputs[(long)b * ROWLEN];
    float t2 = t * t;
    float t3 = t2 * t;
    float* dst = &g_basis[b * SDIM];
    dst[0] = 1.0f;
    dst[1] = t;
    dst[2] = t2;
    dst[3] = t3;
    const float knots[4] = {0.2f, 0.4f, 0.6f, 0.8f};
#pragma unroll
    for (int j = 0; j < 4; ++j) {
        float u = t - knots[j];
        u = fmaxf(u, 0.0f);
        dst[4 + j] = u * u * u;
    }
}

// ---------------------------------------------------------------------------
// Fused GEMM: out = X @ W' + basis @ b_wts
//   X[b, s*512+i] = basis[b,s] * features[b,i]   (generated on the fly)
//   W'[k, o]      = W_wts flat, row-major (4096, 512)
// ---------------------------------------------------------------------------
__global__ __launch_bounds__(NTHREADS)
void vclinear_gemm_kernel(const float* __restrict__ inputs,
                          const float* __restrict__ W,
                          const float* __restrict__ bwts,
                          float* __restrict__ out) {
    __shared__ __align__(16) float sA[BK][SA_STRIDE];   // transposed A tile [k][m]
    __shared__ __align__(16) float sB[BK][BN];
    __shared__ __align__(16) float sBasis[BM][SDIM];

    const int tid     = threadIdx.x;
    const int block_m = blockIdx.y * BM;
    const int block_n = blockIdx.x * BN;

    // Load this block's basis rows (128 x 8 = 4KB)
    for (int idx = tid; idx < BM * SDIM; idx += NTHREADS) {
        sBasis[idx / SDIM][idx % SDIM] = g_basis[(block_m + idx / SDIM) * SDIM + (idx % SDIM)];
    }

    // Micro-tile coords
    const int tx  = tid & 15;   // N direction (16 * TN = 64)
    const int ty  = tid >> 4;   // M direction (16 * TM = 128)
    const int tm0 = ty * TM;
    const int tn0 = tx * TN;

    // A global-load mapping: each pass covers 16 rows x 16 cols; 8 passes for BM=128
    const int a_col  = tid & 15;    // k within tile
    const int a_row0 = tid >> 4;    // 0..15
    // B global-load mapping: 16 rows x 64 cols as 256 float4, 1 per thread
    const int b_row  = tid >> 4;
    const int b_col4 = (tid & 15) * 4;

    float acc[TM][TN];
#pragma unroll
    for (int i = 0; i < TM; ++i)
#pragma unroll
        for (int j = 0; j < TN; ++j) acc[i][j] = 0.0f;

    float  a_reg[BM / 16];
    float4 b_reg;

    // --- prologue: load tile 0 ---
    {
        const int i0 = 0;
#pragma unroll
        for (int p = 0; p < BM / 16; ++p) {
            int r = a_row0 + p * 16;
            a_reg[p] = __ldg(&inputs[(long)(block_m + r) * ROWLEN + 1 + i0 + a_col]);
        }
        b_reg = *reinterpret_cast<const float4*>(&W[(long)b_row * OUT_DIM + block_n + b_col4]);
    }
    __syncthreads();   // sBasis ready
    {
        const int s = 0;
#pragma unroll
        for (int p = 0; p < BM / 16; ++p) {
            int r = a_row0 + p * 16;
            sA[a_col][r] = a_reg[p] * sBasis[r][s];
        }
        *reinterpret_cast<float4*>(&sB[b_row][b_col4]) = b_reg;
    }
    __syncthreads();

    for (int t = 0; t < NTILES; ++t) {
        // prefetch next tile into registers (overlaps with compute below)
        if (t + 1 < NTILES) {
            const int k0 = (t + 1) * BK;
            const int i0 = k0 & (IN_DIM - 1);
#pragma unroll
            for (int p = 0; p < BM / 16; ++p) {
                int r = a_row0 + p * 16;
                a_reg[p] = __ldg(&inputs[(long)(block_m + r) * ROWLEN + 1 + i0 + a_col]);
            }
            b_reg = *reinterpret_cast<const float4*>(
                &W[(long)(k0 + b_row) * OUT_DIM + block_n + b_col4]);
        }

        // compute on current smem tile
#pragma unroll
        for (int kk = 0; kk < BK; ++kk) {
            float4 a0 = *reinterpret_cast<const float4*>(&sA[kk][tm0]);
            float4 a1 = *reinterpret_cast<const float4*>(&sA[kk][tm0 + 4]);
            float4 b4 = *reinterpret_cast<const float4*>(&sB[kk][tn0]);
            float am[TM] = {a0.x, a0.y, a0.z, a0.w, a1.x, a1.y, a1.z, a1.w};
            float bn[TN] = {b4.x, b4.y, b4.z, b4.w};
#pragma unroll
            for (int i = 0; i < TM; ++i)
#pragma unroll
                for (int j = 0; j < TN; ++j)
                    acc[i][j] = fmaf(am[i], bn[j], acc[i][j]);
        }
        __syncthreads();

        if (t + 1 < NTILES) {
            const int s = ((t + 1) * BK) >> 9;   // basis index, constant per tile
#pragma unroll
            for (int p = 0; p < BM / 16; ++p) {
                int r = a_row0 + p * 16;
                sA[a_col][r] = a_reg[p] * sBasis[r][s];
            }
            *reinterpret_cast<float4*>(&sB[b_row][b_col4]) = b_reg;
        }
        __syncthreads();
    }

    // --- epilogue: add bias = basis @ b_wts, vectorized store ---
#pragma unroll
    for (int i = 0; i < TM; ++i) {
        const int r = tm0 + i;
        float bias[TN] = {0.0f, 0.0f, 0.0f, 0.0f};
#pragma unroll
        for (int s2 = 0; s2 < SDIM; ++s2) {
            float bsv = sBasis[r][s2];
            const float* bw = &bwts[s2 * OUT_DIM + block_n + tn0];
#pragma unroll
            for (int j = 0; j < TN; ++j)
                bias[j] = fmaf(bsv, __ldg(&bw[j]), bias[j]);
        }
        float4 o4;
        o4.x = acc[i][0] + bias[0];
        o4.y = acc[i][1] + bias[1];
        o4.z = acc[i][2] + bias[2];
        o4.w = acc[i][3] + bias[3];
        *reinterpret_cast<float4*>(&out[(long)(block_m + r) * OUT_DIM + block_n + tn0]) = o4;
    }
}

// ---------------------------------------------------------------------------
extern "C" void kernel_launch(void* const* d_in, const int* in_sizes, int n_in,
                              void* d_out, int out_size) {
    const float* inputs = (const float*)d_in[0];   // (2048, 513)
    const float* W      = (const float*)d_in[1];   // (8, 512*512) == (4096, 512) flat
    const float* bwts   = (const float*)d_in[2];   // (8, 512)
    float* out          = (float*)d_out;           // (2048, 512)

    basis_kernel<<<(BATCH + 255) / 256, 256>>>(inputs);

    dim3 grid(OUT_DIM / BN, BATCH / BM);   // (8, 16) = 128 CTAs
    vclinear_gemm_kernel<<<grid, NTHREADS>>>(inputs, W, bwts, out);
}

// round 3
// speedup vs baseline: 2.4315x; 2.4315x over previous
#include <cuda_runtime.h>
#include <cuda_bf16.h>
#include <cstdint>

#define BATCH   2048
#define IN_DIM  512
#define OUT_DIM 512
#define SDIM    8
#define KDIM    4096
#define ROWLEN  513

#define BM 128
#define BN 64
#define BK 32
#define STAGES 4
#define NTH 256
#define KSTEPS (KDIM / BK)          // 128

// SMEM geometry: rows padded to 40 bf16 (80 bytes) -> conflict-free ldmatrix
#define SROWB 80
#define A_BYTES (BM * SROWB)        // 10240
#define B_BYTES (BN * SROWB)        // 5120
#define STAGE_BYTES (2 * A_BYTES + 2 * B_BYTES)   // 30720
#define OFF_AHI 0
#define OFF_ALO A_BYTES
#define OFF_BHI (2 * A_BYTES)
#define OFF_BLO (2 * A_BYTES + B_BYTES)
#define OFF_BASIS (STAGES * STAGE_BYTES)          // 122880
#define OFF_BW (OFF_BASIS + BM * SDIM * 4)        // +4096
#define SMEM_TOTAL (OFF_BW + SDIM * BN * 4)       // 129024

// ---------------------------------------------------------------------------
__device__ __forceinline__ uint32_t smem_u32(const void* p) {
    uint32_t a;
    asm("{ .reg .u64 t; cvta.to.shared.u64 t, %1; cvt.u32.u64 %0, t; }"
        : "=r"(a) : "l"(p));
    return a;
}
__device__ __forceinline__ void cp16(uint32_t dst, const void* src) {
    asm volatile("cp.async.cg.shared.global [%0], [%1], 16;"
                 :: "r"(dst), "l"(src) : "memory");
}
#define CP_COMMIT() asm volatile("cp.async.commit_group;" ::: "memory")
#define CP_WAIT(n)  asm volatile("cp.async.wait_group %0;" :: "n"(n) : "memory")

__device__ __forceinline__ void ldm_x4(uint32_t* r, uint32_t addr) {
    asm volatile("ldmatrix.sync.aligned.m8n8.x4.shared.b16 {%0,%1,%2,%3}, [%4];"
                 : "=r"(r[0]), "=r"(r[1]), "=r"(r[2]), "=r"(r[3]) : "r"(addr));
}
__device__ __forceinline__ void mma_bf16(float* d, const uint32_t* a, const uint32_t* b) {
    asm volatile(
        "mma.sync.aligned.m16n8k16.row.col.f32.bf16.bf16.f32 "
        "{%0,%1,%2,%3}, {%4,%5,%6,%7}, {%8,%9}, {%0,%1,%2,%3};"
        : "+f"(d[0]), "+f"(d[1]), "+f"(d[2]), "+f"(d[3])
        : "r"(a[0]), "r"(a[1]), "r"(a[2]), "r"(a[3]), "r"(b[0]), "r"(b[1]));
}

// ---------------------------------------------------------------------------
// Device scratch
// ---------------------------------------------------------------------------
__device__ float g_basis[BATCH * SDIM];
__device__ __align__(16) __nv_bfloat16 g_X_hi[BATCH * KDIM];   // X = basis*feat
__device__ __align__(16) __nv_bfloat16 g_X_lo[BATCH * KDIM];
__device__ __align__(16) __nv_bfloat16 g_Wt_hi[OUT_DIM * KDIM]; // Wt[o][s*512+i]
__device__ __align__(16) __nv_bfloat16 g_Wt_lo[OUT_DIM * KDIM];

// ---------------------------------------------------------------------------
// Prep 1: X[b][k] = basis[b][k>>9] * feat[b][k&511], split to bf16 hi/lo
// ---------------------------------------------------------------------------
__global__ void prep_x_kernel(const float* __restrict__ inputs) {
    const int b   = blockIdx.x;
    const int tid = threadIdx.x;
    float t  = __ldg(&inputs[(size_t)b * ROWLEN]);
    float t2 = t * t, t3 = t2 * t;
    float bs[SDIM];
    bs[0] = 1.0f; bs[1] = t; bs[2] = t2; bs[3] = t3;
    const float kn[4] = {0.2f, 0.4f, 0.6f, 0.8f};
#pragma unroll
    for (int j = 0; j < 4; ++j) {
        float u = fmaxf(t - kn[j], 0.0f);
        bs[4 + j] = u * u * u;
    }
    if (tid < SDIM) g_basis[b * SDIM + tid] = bs[tid];

    const int k0 = tid * 16;                 // 16 elems per thread, same s
    const int s  = k0 >> 9;
    const float f = bs[s];
    const float* src = inputs + (size_t)b * ROWLEN + 1 + (k0 & 511);
    __nv_bfloat16 hi[16], lo[16];
#pragma unroll
    for (int j = 0; j < 16; ++j) {
        float x = __ldg(&src[j]) * f;
        __nv_bfloat16 h = __float2bfloat16(x);
        hi[j] = h;
        lo[j] = __float2bfloat16(x - __bfloat162float(h));
    }
    const size_t o = (size_t)b * KDIM + k0;
#pragma unroll
    for (int j = 0; j < 2; ++j) {
        ((uint4*)(g_X_hi + o))[j] = ((uint4*)hi)[j];
        ((uint4*)(g_X_lo + o))[j] = ((uint4*)lo)[j];
    }
}

// ---------------------------------------------------------------------------
// Prep 2: Wt[o][s*512+i] = W[s][i][o], bf16 hi/lo
// ---------------------------------------------------------------------------
__global__ void prep_w_kernel(const float* __restrict__ W) {
    __shared__ float t[32][33];
    const int s  = blockIdx.z;
    const int i0 = blockIdx.x * 32, o0 = blockIdx.y * 32;
    const int tx = threadIdx.x, ty = threadIdx.y;
    for (int r = ty; r < 32; r += 8)
        t[r][tx] = W[((size_t)s << 18) + (size_t)(i0 + r) * 512 + o0 + tx];
    __syncthreads();
    for (int r = ty; r < 32; r += 8) {
        float x = t[tx][r];                 // = W[s][i0+tx][o0+r]
        __nv_bfloat16 h = __float2bfloat16(x);
        size_t oidx = (size_t)(o0 + r) * KDIM + s * 512 + i0 + tx;
        g_Wt_hi[oidx] = h;
        g_Wt_lo[oidx] = __float2bfloat16(x - __bfloat162float(h));
    }
}

// ---------------------------------------------------------------------------
// Main GEMM: out(2048x512) = X @ Wt^T (+ basis @ b_wts), bf16 3-pass HMMA
// ---------------------------------------------------------------------------
__global__ __launch_bounds__(NTH, 1)
void vclinear_mma_kernel(const float* __restrict__ bwts, float* __restrict__ out) {
    extern __shared__ char smem[];
    const uint32_t sb = smem_u32(smem);
    const int tid  = threadIdx.x;
    const int wid  = tid >> 5;
    const int lane = tid & 31;
    const int block_n = blockIdx.x * BN;
    const int block_m = blockIdx.y * BM;

    // stage basis + bias slice into smem (read in epilogue only)
    float* sBasis = (float*)(smem + OFF_BASIS);
    float* sBw    = (float*)(smem + OFF_BW);
    for (int q = tid; q < BM * SDIM; q += NTH)
        sBasis[q] = g_basis[(block_m + (q >> 3)) * SDIM + (q & 7)];
    for (int q = tid; q < SDIM * BN; q += NTH)
        sBw[q] = bwts[(q >> 6) * OUT_DIM + block_n + (q & 63)];

    // per-thread cp.async chunk mapping
    const int a_row0 = tid >> 2;            // + 64 for second chunk
    const int a_c    = tid & 3;
    const int b_row  = tid >> 2;            // 0..63
    const size_t gA0 = (size_t)(block_m + a_row0) * KDIM + a_c * 8;
    const size_t gA1 = (size_t)(block_m + a_row0 + 64) * KDIM + a_c * 8;
    const size_t gB  = (size_t)(block_n + b_row) * KDIM + a_c * 8;
    const uint32_t dA0 = a_row0 * SROWB + a_c * 16;
    const uint32_t dA1 = (a_row0 + 64) * SROWB + a_c * 16;
    const uint32_t dB  = b_row * SROWB + a_c * 16;

#define LOAD_STAGE(ks, buf) do {                                               \
    const uint32_t s0 = sb + (buf) * STAGE_BYTES;                              \
    const int kofs = (ks) * BK;                                                \
    cp16(s0 + OFF_AHI + dA0, g_X_hi + gA0 + kofs);                             \
    cp16(s0 + OFF_AHI + dA1, g_X_hi + gA1 + kofs);                             \
    cp16(s0 + OFF_ALO + dA0, g_X_lo + gA0 + kofs);                             \
    cp16(s0 + OFF_ALO + dA1, g_X_lo + gA1 + kofs);                             \
    cp16(s0 + OFF_BHI + dB,  g_Wt_hi + gB + kofs);                             \
    cp16(s0 + OFF_BLO + dB,  g_Wt_lo + gB + kofs);                             \
} while (0)

    // warp tiling: 4 (m) x 2 (n) warps, each 32x32
    const int m0 = (wid & 3) * 32;
    const int n0 = (wid >> 2) * 32;
    // ldmatrix relative offsets
    const uint32_t aoff = (m0 + (lane & 15)) * SROWB + (lane >> 4) * 16;
    const uint32_t boff = (n0 + (lane & 7) + ((lane >> 4) << 3)) * SROWB
                        + ((lane >> 3) & 1) * 16;

    float acc[2][4][4];
#pragma unroll
    for (int i = 0; i < 2; ++i)
#pragma unroll
        for (int j = 0; j < 4; ++j)
#pragma unroll
            for (int r = 0; r < 4; ++r) acc[i][j][r] = 0.0f;

    // prologue
#pragma unroll
    for (int st = 0; st < STAGES - 1; ++st) {
        LOAD_STAGE(st, st);
        CP_COMMIT();
    }

    for (int ks = 0; ks < KSTEPS; ++ks) {
        CP_WAIT(STAGES - 2);
        __syncthreads();

        const int nxt = ks + STAGES - 1;
        if (nxt < KSTEPS) LOAD_STAGE(nxt, nxt & (STAGES - 1));
        CP_COMMIT();

        const uint32_t s0 = sb + (ks & (STAGES - 1)) * STAGE_BYTES;
#pragma unroll
        for (int kk = 0; kk < BK; kk += 16) {
            uint32_t ah[2][4], al[2][4], bh[2][4], bl[2][4];
            ldm_x4(ah[0], s0 + OFF_AHI + aoff + kk * 2);
            ldm_x4(ah[1], s0 + OFF_AHI + aoff + kk * 2 + 16 * SROWB);
            ldm_x4(al[0], s0 + OFF_ALO + aoff + kk * 2);
            ldm_x4(al[1], s0 + OFF_ALO + aoff + kk * 2 + 16 * SROWB);
            ldm_x4(bh[0], s0 + OFF_BHI + boff + kk * 2);
            ldm_x4(bh[1], s0 + OFF_BHI + boff + kk * 2 + 16 * SROWB);
            ldm_x4(bl[0], s0 + OFF_BLO + boff + kk * 2);
            ldm_x4(bl[1], s0 + OFF_BLO + boff + kk * 2 + 16 * SROWB);
#pragma unroll
            for (int tm = 0; tm < 2; ++tm)
#pragma unroll
                for (int tn = 0; tn < 4; ++tn) {
                    const uint32_t* bhp = &bh[tn >> 1][(tn & 1) * 2];
                    const uint32_t* blp = &bl[tn >> 1][(tn & 1) * 2];
                    mma_bf16(acc[tm][tn], ah[tm], bhp);   // hh
                    mma_bf16(acc[tm][tn], ah[tm], blp);   // hl
                    mma_bf16(acc[tm][tn], al[tm], bhp);   // lh
                }
        }
    }

    // epilogue: bias = basis @ b_wts, fused add, float2 stores
#pragma unroll
    for (int tm = 0; tm < 2; ++tm) {
        const int rbase = m0 + tm * 16 + (lane >> 2);
#pragma unroll
        for (int half = 0; half < 2; ++half) {
            const int row = rbase + half * 8;
            float bs[SDIM];
#pragma unroll
            for (int s = 0; s < SDIM; ++s) bs[s] = sBasis[row * SDIM + s];
#pragma unroll
            for (int tn = 0; tn < 4; ++tn) {
                const int col = tn * 8 + 2 * (lane & 3) + n0;
                float b0 = 0.0f, b1 = 0.0f;
#pragma unroll
                for (int s = 0; s < SDIM; ++s) {
                    b0 = fmaf(bs[s], sBw[s * BN + col], b0);
                    b1 = fmaf(bs[s], sBw[s * BN + col + 1], b1);
                }
                float2 v;
                v.x = acc[tm][tn][half * 2 + 0] + b0;
                v.y = acc[tm][tn][half * 2 + 1] + b1;
                *(float2*)&out[(size_t)(block_m + row) * OUT_DIM + block_n + col] = v;
            }
        }
    }
}

// ---------------------------------------------------------------------------
extern "C" void kernel_launch(void* const* d_in, const int* in_sizes, int n_in,
                              void* d_out, int out_size) {
    const float* inputs = (const float*)d_in[0];   // (2048, 513)
    const float* W      = (const float*)d_in[1];   // (8, 512*512)
    const float* bwts   = (const float*)d_in[2];   // (8, 512)
    float* out          = (float*)d_out;           // (2048, 512)

    cudaFuncSetAttribute(vclinear_mma_kernel,
                         cudaFuncAttributeMaxDynamicSharedMemorySize, SMEM_TOTAL);

    prep_x_kernel<<<BATCH, 256>>>(inputs);
    dim3 gw(16, 16, 8), bw(32, 8);
    prep_w_kernel<<<gw, bw>>>(W);

    dim3 grid(OUT_DIM / BN, BATCH / BM);   // (8, 16) = 128 CTAs
    vclinear_mma_kernel<<<grid, NTH, SMEM_TOTAL>>>(bwts, out);
}

// round 4
// speedup vs baseline: 5.4515x; 2.2420x over previous
#include <cuda_runtime.h>
#include <cuda_fp16.h>
#include <cstdint>

#define BATCH   2048
#define IN_DIM  512
#define OUT_DIM 512
#define SDIM    8
#define KDIM    4096
#define ROWLEN  513

#define BM 128
#define BN 64
#define BK 32
#define STAGES 4
#define NTH 128
#define KSTEPS (KDIM / BK)          // 128

// rows padded to 40 fp16 (80B): 80 = 16*5, 5 coprime 8 -> conflict-free ldmatrix
#define SROWB 80
#define A_BYTES (BM * SROWB)        // 10240
#define B_BYTES (BN * SROWB)        // 5120
#define STAGE_BYTES (A_BYTES + B_BYTES)           // 15360
#define OFF_B A_BYTES
#define OFF_BASIS (STAGES * STAGE_BYTES)          // 61440
#define OFF_BW (OFF_BASIS + BM * SDIM * 4)        // 65536
#define SMEM_TOTAL (OFF_BW + SDIM * BN * 4)       // 67584

// ---------------------------------------------------------------------------
__device__ __forceinline__ uint32_t smem_u32(const void* p) {
    uint32_t a;
    asm("{ .reg .u64 t; cvta.to.shared.u64 t, %1; cvt.u32.u64 %0, t; }"
        : "=r"(a) : "l"(p));
    return a;
}
__device__ __forceinline__ void cp16(uint32_t dst, const void* src) {
    asm volatile("cp.async.cg.shared.global [%0], [%1], 16;"
                 :: "r"(dst), "l"(src) : "memory");
}
#define CP_COMMIT() asm volatile("cp.async.commit_group;" ::: "memory")
#define CP_WAIT(n)  asm volatile("cp.async.wait_group %0;" :: "n"(n) : "memory")

__device__ __forceinline__ void ldm_x4(uint32_t* r, uint32_t addr) {
    asm volatile("ldmatrix.sync.aligned.m8n8.x4.shared.b16 {%0,%1,%2,%3}, [%4];"
                 : "=r"(r[0]), "=r"(r[1]), "=r"(r[2]), "=r"(r[3]) : "r"(addr));
}
__device__ __forceinline__ void mma_f16(float* d, const uint32_t* a, const uint32_t* b) {
    asm volatile(
        "mma.sync.aligned.m16n8k16.row.col.f32.f16.f16.f32 "
        "{%0,%1,%2,%3}, {%4,%5,%6,%7}, {%8,%9}, {%0,%1,%2,%3};"
        : "+f"(d[0]), "+f"(d[1]), "+f"(d[2]), "+f"(d[3])
        : "r"(a[0]), "r"(a[1]), "r"(a[2]), "r"(a[3]), "r"(b[0]), "r"(b[1]));
}

// ---------------------------------------------------------------------------
// Device scratch
// ---------------------------------------------------------------------------
__device__ float g_basis[BATCH * SDIM];
__device__ __align__(16) __half g_X[BATCH * KDIM];      // X[b][s*512+i] = basis*feat
__device__ __align__(16) __half g_Wt[OUT_DIM * KDIM];   // Wt[o][s*512+i] = W[s][i][o]

// ---------------------------------------------------------------------------
// Prep 1: X fp16, coalesced uint32 stores (2 halves per thread per iter)
// ---------------------------------------------------------------------------
__global__ void prep_x_kernel(const float* __restrict__ inputs) {
    const int b   = blockIdx.x;
    const int tid = threadIdx.x;
    const float* row = inputs + (size_t)b * ROWLEN;
    float t  = __ldg(row);
    float t2 = t * t, t3 = t2 * t;
    float bs[SDIM];
    bs[0] = 1.0f; bs[1] = t; bs[2] = t2; bs[3] = t3;
    const float kn[4] = {0.2f, 0.4f, 0.6f, 0.8f};
#pragma unroll
    for (int j = 0; j < 4; ++j) {
        float u = fmaxf(t - kn[j], 0.0f);
        bs[4 + j] = u * u * u;
    }
    if (tid < SDIM) g_basis[b * SDIM + tid] = bs[tid];

    uint32_t* dst = (uint32_t*)(g_X + (size_t)b * KDIM);
    const float* feat = row + 1;
#pragma unroll
    for (int it = 0; it < KDIM / 2 / 256; ++it) {      // 8 iters
        int p = it * 256 + tid;                        // uint32 index
        int k = p * 2;
        int s = k >> 9;
        float f = bs[s];
        int i = k & 511;
        float x0 = __ldg(&feat[i]) * f;
        float x1 = __ldg(&feat[i + 1]) * f;
        __half2 h = __floats2half2_rn(x0, x1);
        dst[p] = *(uint32_t*)&h;
    }
}

// ---------------------------------------------------------------------------
// Prep 2: Wt[o][s*512+i] = W[s][i][o], fp16, coalesced both sides
// ---------------------------------------------------------------------------
__global__ void prep_w_kernel(const float* __restrict__ W) {
    __shared__ float t[64][33];
    const int s  = blockIdx.z;
    const int i0 = blockIdx.x * 64, o0 = blockIdx.y * 32;
    const int tx = threadIdx.x, ty = threadIdx.y;
    for (int r = ty; r < 64; r += 8)
        t[r][tx] = W[((size_t)s << 18) + (size_t)(i0 + r) * 512 + o0 + tx];
    __syncthreads();
    for (int r = ty; r < 32; r += 8) {
        __half2 h = __floats2half2_rn(t[2 * tx][r], t[2 * tx + 1][r]);
        *(uint32_t*)&g_Wt[(size_t)(o0 + r) * KDIM + s * 512 + i0 + 2 * tx] =
            *(uint32_t*)&h;
    }
}

// ---------------------------------------------------------------------------
// Main GEMM: out = X @ Wt^T + basis @ b_wts; single-pass fp16 HMMA.
// CTA 128x64, 4 warps (2m x 2n), warp tile 64x32, BK=32, 4-stage cp.async.
// ---------------------------------------------------------------------------
__global__ __launch_bounds__(NTH, 1)
void vclinear_mma_kernel(const float* __restrict__ bwts, float* __restrict__ out) {
    extern __shared__ char smem[];
    const uint32_t sb = smem_u32(smem);
    const int tid  = threadIdx.x;
    const int wid  = tid >> 5;
    const int lane = tid & 31;
    const int block_n = blockIdx.x * BN;
    const int block_m = blockIdx.y * BM;

    float* sBasis = (float*)(smem + OFF_BASIS);
    float* sBw    = (float*)(smem + OFF_BW);
    for (int q = tid; q < BM * SDIM; q += NTH)
        sBasis[q] = g_basis[(block_m + (q >> 3)) * SDIM + (q & 7)];
    for (int q = tid; q < SDIM * BN; q += NTH)
        sBw[q] = bwts[(q >> 6) * OUT_DIM + block_n + (q & 63)];

    // cp.async mapping: A 512 16B-chunks, B 256 chunks, 128 threads
    const int c  = tid & 3;                 // 16B chunk within 64B row data
    const int r0 = tid >> 2;                // 0..31

#define LOAD_STAGE(ks, buf) do {                                               \
    const uint32_t s0 = sb + (buf) * STAGE_BYTES;                              \
    const size_t kofs = (size_t)(ks) * BK + c * 8;                             \
    _Pragma("unroll")                                                          \
    for (int j = 0; j < 4; ++j) {                                              \
        int row = r0 + j * 32;                                                 \
        cp16(s0 + row * SROWB + c * 16,                                        \
             g_X + (size_t)(block_m + row) * KDIM + kofs);                     \
    }                                                                          \
    _Pragma("unroll")                                                          \
    for (int j = 0; j < 2; ++j) {                                              \
        int row = r0 + j * 32;                                                 \
        cp16(s0 + OFF_B + row * SROWB + c * 16,                                \
             g_Wt + (size_t)(block_n + row) * KDIM + kofs);                    \
    }                                                                          \
} while (0)

    // warp tiling: 2m x 2n, warp tile 64x32
    const int m0 = (wid >> 1) * 64;
    const int n0 = (wid & 1) * 32;
    const uint32_t aoff = (m0 + (lane & 15)) * SROWB + (lane >> 4) * 16;
    const uint32_t boff = (n0 + (lane & 7) + ((lane >> 4) << 3)) * SROWB
                        + ((lane >> 3) & 1) * 16;

    float acc[4][4][4];
#pragma unroll
    for (int i = 0; i < 4; ++i)
#pragma unroll
        for (int j = 0; j < 4; ++j)
#pragma unroll
            for (int r = 0; r < 4; ++r) acc[i][j][r] = 0.0f;

#pragma unroll
    for (int st = 0; st < STAGES - 1; ++st) {
        LOAD_STAGE(st, st);
        CP_COMMIT();
    }

    for (int ks = 0; ks < KSTEPS; ++ks) {
        CP_WAIT(STAGES - 2);
        __syncthreads();

        const int nxt = ks + STAGES - 1;
        if (nxt < KSTEPS) LOAD_STAGE(nxt, nxt & (STAGES - 1));
        CP_COMMIT();

        const uint32_t s0 = sb + (ks & (STAGES - 1)) * STAGE_BYTES;
#pragma unroll
        for (int kk = 0; kk < BK; kk += 16) {
            uint32_t a[4][4], b[2][4];
#pragma unroll
            for (int ma = 0; ma < 4; ++ma)
                ldm_x4(a[ma], s0 + aoff + ma * 16 * SROWB + kk * 2);
#pragma unroll
            for (int nb = 0; nb < 2; ++nb)
                ldm_x4(b[nb], s0 + OFF_B + boff + nb * 16 * SROWB + kk * 2);
#pragma unroll
            for (int ma = 0; ma < 4; ++ma)
#pragma unroll
                for (int na = 0; na < 4; ++na)
                    mma_f16(acc[ma][na], a[ma], &b[na >> 1][(na & 1) * 2]);
        }
    }

    // epilogue: fused bias = basis @ b_wts
#pragma unroll
    for (int ma = 0; ma < 4; ++ma) {
        const int rbase = m0 + ma * 16 + (lane >> 2);
#pragma unroll
        for (int half = 0; half < 2; ++half) {
            const int row = rbase + half * 8;
            float bsv[SDIM];
#pragma unroll
            for (int s = 0; s < SDIM; ++s) bsv[s] = sBasis[row * SDIM + s];
#pragma unroll
            for (int na = 0; na < 4; ++na) {
                const int col = n0 + na * 8 + 2 * (lane & 3);
                float b0 = 0.0f, b1 = 0.0f;
#pragma unroll
                for (int s = 0; s < SDIM; ++s) {
                    b0 = fmaf(bsv[s], sBw[s * BN + col], b0);
                    b1 = fmaf(bsv[s], sBw[s * BN + col + 1], b1);
                }
                float2 v;
                v.x = acc[ma][na][half * 2 + 0] + b0;
                v.y = acc[ma][na][half * 2 + 1] + b1;
                *(float2*)&out[(size_t)(block_m + row) * OUT_DIM + block_n + col] = v;
            }
        }
    }
}

// ---------------------------------------------------------------------------
extern "C" void kernel_launch(void* const* d_in, const int* in_sizes, int n_in,
                              void* d_out, int out_size) {
    const float* inputs = (const float*)d_in[0];   // (2048, 513)
    const float* W      = (const float*)d_in[1];   // (8, 512*512)
    const float* bwts   = (const float*)d_in[2];   // (8, 512)
    float* out          = (float*)d_out;           // (2048, 512)

    cudaFuncSetAttribute(vclinear_mma_kernel,
                         cudaFuncAttributeMaxDynamicSharedMemorySize, SMEM_TOTAL);

    prep_x_kernel<<<BATCH, 256>>>(inputs);
    dim3 gw(8, 16, 8), bw(32, 8);
    prep_w_kernel<<<gw, bw>>>(W);

    dim3 grid(OUT_DIM / BN, BATCH / BM);   // (8, 16) = 128 CTAs
    vclinear_mma_kernel<<<grid, NTH, SMEM_TOTAL>>>(bwts, out);
}